// round 4
// baseline (speedup 1.0000x reference)
#include <cuda_runtime.h>
#include <cuda_bf16.h>
#include <stdint.h>

// PeriodicDistance — quantized gathers via ld.global.cg (L2-only), trimmed
// 3-launch pipeline, streaming stores.
//
// Output layout (float32, flattened tuple in return order):
//   [0,E) ei0 | [E,2E) ei1 | [2E,3E) weight | [3E,6E) vec[E,3] | [6E,9E) shifts[E,3]

#define MAX_ATOMS_PAD (1 << 19)      // 524288 atoms * 8B = 4 MB scratch
#define MM_BLOCKS 592                // minmax grid (4 blocks/SM)
__device__ uint2 g_posq[MAX_ATOMS_PAD];
__device__ uint2 g_blkmm[MM_BLOCKS]; // per-block (minkey, maxkey) — overwritten each run
__device__ float g_qscale;

// monotone float<->uint keys
__device__ __forceinline__ unsigned f2key(float f) {
    unsigned u = __float_as_uint(f);
    return (u & 0x80000000u) ? ~u : (u | 0x80000000u);
}
__device__ __forceinline__ float key2f(unsigned k) {
    unsigned u = (k & 0x80000000u) ? (k ^ 0x80000000u) : ~k;
    return __uint_as_float(u);
}

// L2-only 8B gather
__device__ __forceinline__ uint2 ldcg_u2(const uint2* p) {
    uint2 r;
    asm volatile("ld.global.cg.v2.u32 {%0,%1}, [%2];"
                 : "=r"(r.x), "=r"(r.y) : "l"(p));
    return r;
}

// ---- k1: per-block minmax of pos (no global reset needed: slots overwritten) ----
__global__ void __launch_bounds__(256)
pd_minmax(const float* __restrict__ pos, int n_f)
{
    float lo = 3.4e38f, hi = -3.4e38f;
    int n4 = n_f >> 2;
    const float4* p4 = (const float4*)pos;
    for (int i = blockIdx.x * blockDim.x + threadIdx.x; i < n4;
         i += gridDim.x * blockDim.x) {
        float4 v = __ldg(p4 + i);
        lo = fminf(lo, fminf(fminf(v.x, v.y), fminf(v.z, v.w)));
        hi = fmaxf(hi, fmaxf(fmaxf(v.x, v.y), fmaxf(v.z, v.w)));
    }
    // tail
    for (int i = (n4 << 2) + blockIdx.x * blockDim.x + threadIdx.x; i < n_f;
         i += gridDim.x * blockDim.x) {
        float v = __ldg(pos + i);
        lo = fminf(lo, v); hi = fmaxf(hi, v);
    }
    for (int o = 16; o > 0; o >>= 1) {
        lo = fminf(lo, __shfl_xor_sync(0xFFFFFFFFu, lo, o));
        hi = fmaxf(hi, __shfl_xor_sync(0xFFFFFFFFu, hi, o));
    }
    __shared__ float slo[8], shi[8];
    int w = threadIdx.x >> 5, l = threadIdx.x & 31;
    if (l == 0) { slo[w] = lo; shi[w] = hi; }
    __syncthreads();
    if (threadIdx.x == 0) {
        for (int k = 1; k < 8; k++) { lo = fminf(lo, slo[k]); hi = fmaxf(hi, shi[k]); }
        g_blkmm[blockIdx.x] = make_uint2(f2key(lo), f2key(hi));
    }
}

// ---- k2: reduce slots (redundantly per block), quantize, publish scale ----
__global__ void __launch_bounds__(256)
pd_quant(const float* __restrict__ pos, int n_atoms)
{
    __shared__ float s_qmin, s_qinv;
    if (threadIdx.x < 32) {
        unsigned mk = 0xFFFFFFFFu, xk = 0u;
        for (int i = threadIdx.x; i < MM_BLOCKS; i += 32) {
            uint2 v = g_blkmm[i];
            mk = min(mk, v.x); xk = max(xk, v.y);
        }
        for (int o = 16; o > 0; o >>= 1) {
            mk = min(mk, __shfl_xor_sync(0xFFFFFFFFu, mk, o));
            xk = max(xk, __shfl_xor_sync(0xFFFFFFFFu, xk, o));
        }
        if (threadIdx.x == 0) {
            float lo = key2f(mk), hi = key2f(xk);
            float range = hi - lo;
            if (!(range > 1e-20f)) range = 1.0f;
            s_qmin = lo;
            s_qinv = 65535.0f / range;
            if (blockIdx.x == 0) g_qscale = range / 65535.0f;
        }
    }
    __syncthreads();
    int a = blockIdx.x * blockDim.x + threadIdx.x;
    if (a >= n_atoms) return;
    float qmin = s_qmin, qinv = s_qinv;
    const float* p = pos + 3u * (size_t)a;
    float x = __ldg(p + 0), y = __ldg(p + 1), z = __ldg(p + 2);
    unsigned ux = (unsigned)min(65535.0f, fmaxf(0.0f, fmaf(x - qmin, qinv, 0.5f)));
    unsigned uy = (unsigned)min(65535.0f, fmaxf(0.0f, fmaf(y - qmin, qinv, 0.5f)));
    unsigned uz = (unsigned)min(65535.0f, fmaxf(0.0f, fmaf(z - qmin, qinv, 0.5f)));
    g_posq[a] = make_uint2(ux | (uy << 16), uz);
}

// ---- k3: main — 4 edges/thread, .cg gathers, streaming float4 stores ----
__global__ void __launch_bounds__(256)
pd_kernel_q4(const float* __restrict__ box,
             const int*   __restrict__ ei,
             const int*   __restrict__ shifts,
             float*       __restrict__ out,
             int E4)
{
    int t = blockIdx.x * blockDim.x + threadIdx.x;
    if (t >= E4) return;

    size_t Es = 4u * (size_t)E4;

    const int4* ei4 = (const int4*)ei;
    int4 ia = __ldg(ei4 + t);
    int4 ib = __ldg(ei4 + E4 + t);

    // issue all 8 gathers first (max MLP, L2-only path)
    uint2 qa0 = ldcg_u2(&g_posq[ia.x]);
    uint2 qa1 = ldcg_u2(&g_posq[ia.y]);
    uint2 qa2 = ldcg_u2(&g_posq[ia.z]);
    uint2 qa3 = ldcg_u2(&g_posq[ia.w]);
    uint2 qb0 = ldcg_u2(&g_posq[ib.x]);
    uint2 qb1 = ldcg_u2(&g_posq[ib.y]);
    uint2 qb2 = ldcg_u2(&g_posq[ib.z]);
    uint2 qb3 = ldcg_u2(&g_posq[ib.w]);

    const int4* sh4 = (const int4*)shifts;
    int4 s0 = __ldg(sh4 + 3u * (size_t)t + 0);
    int4 s1 = __ldg(sh4 + 3u * (size_t)t + 1);
    int4 s2 = __ldg(sh4 + 3u * (size_t)t + 2);
    float fx0 = (float)s0.x, fy0 = (float)s0.y, fz0 = (float)s0.z;
    float fx1 = (float)s0.w, fy1 = (float)s1.x, fz1 = (float)s1.y;
    float fx2 = (float)s1.z, fy2 = (float)s1.w, fz2 = (float)s2.x;
    float fx3 = (float)s2.y, fy3 = (float)s2.z, fz3 = (float)s2.w;

    float b00 = __ldg(box + 0), b01 = __ldg(box + 1), b02 = __ldg(box + 2);
    float b10 = __ldg(box + 3), b11 = __ldg(box + 4), b12 = __ldg(box + 5);
    float b20 = __ldg(box + 6), b21 = __ldg(box + 7), b22 = __ldg(box + 8);

    float s = g_qscale;

#define DR(q_b, q_a, FX, FY, FZ, RX, RY, RZ)                                  \
    {                                                                         \
        int dix = (int)(q_b.x & 0xFFFFu) - (int)(q_a.x & 0xFFFFu);            \
        int diy = (int)(q_b.x >> 16)     - (int)(q_a.x >> 16);                \
        int diz = (int)(q_b.y & 0xFFFFu) - (int)(q_a.y & 0xFFFFu);            \
        RX = fmaf((float)dix, s, FX * b00 + FY * b10 + FZ * b20);             \
        RY = fmaf((float)diy, s, FX * b01 + FY * b11 + FZ * b21);             \
        RZ = fmaf((float)diz, s, FX * b02 + FY * b12 + FZ * b22);             \
    }

    float drx0, dry0, drz0, drx1, dry1, drz1, drx2, dry2, drz2, drx3, dry3, drz3;
    DR(qb0, qa0, fx0, fy0, fz0, drx0, dry0, drz0)
    DR(qb1, qa1, fx1, fy1, fz1, drx1, dry1, drz1)
    DR(qb2, qa2, fx2, fy2, fz2, drx2, dry2, drz2)
    DR(qb3, qa3, fx3, fy3, fz3, drx3, dry3, drz3)
#undef DR

    float4 w = make_float4(
        sqrtf(drx0 * drx0 + dry0 * dry0 + drz0 * drz0),
        sqrtf(drx1 * drx1 + dry1 * dry1 + drz1 * drz1),
        sqrtf(drx2 * drx2 + dry2 * dry2 + drz2 * drz2),
        sqrtf(drx3 * drx3 + dry3 * dry3 + drz3 * drz3));

    float4* o0 = (float4*)(out) + t;
    float4* o1 = (float4*)(out + Es) + t;
    float4* ow = (float4*)(out + 2 * Es) + t;
    float4* ov = (float4*)(out + 3 * Es) + 3u * (size_t)t;
    float4* os = (float4*)(out + 6 * Es) + 3u * (size_t)t;

    __stcs(o0, make_float4((float)ia.x, (float)ia.y, (float)ia.z, (float)ia.w));
    __stcs(o1, make_float4((float)ib.x, (float)ib.y, (float)ib.z, (float)ib.w));
    __stcs(ow, w);
    __stcs(ov + 0, make_float4(-drx0, -dry0, -drz0, -drx1));
    __stcs(ov + 1, make_float4(-dry1, -drz1, -drx2, -dry2));
    __stcs(ov + 2, make_float4(-drz2, -drx3, -dry3, -drz3));
    __stcs(os + 0, make_float4(fx0, fy0, fz0, fx1));
    __stcs(os + 1, make_float4(fy1, fz1, fx2, fy2));
    __stcs(os + 2, make_float4(fz2, fx3, fy3, fz3));
}

// ---- exact scalar fallback (general shapes) ----
__global__ void __launch_bounds__(256)
pd_kernel_full(const float* __restrict__ pos,
               const float* __restrict__ box,
               const int*   __restrict__ ei,
               const int*   __restrict__ shifts,
               const int*   __restrict__ batch,
               float*       __restrict__ out,
               int E, int n_boxes)
{
    int e = blockIdx.x * blockDim.x + threadIdx.x;
    if (e >= E) return;

    int i = __ldg(ei + e);
    int j = __ldg(ei + (size_t)E + e);
    const int* sp = shifts + 3u * (size_t)e;
    float fx = (float)__ldg(sp + 0);
    float fy = (float)__ldg(sp + 1);
    float fz = (float)__ldg(sp + 2);

    const float* b = box;
    if (n_boxes > 1) b = box + 9u * (size_t)__ldg(batch + e);
    float csx = fx * __ldg(b + 0) + fy * __ldg(b + 3) + fz * __ldg(b + 6);
    float csy = fx * __ldg(b + 1) + fy * __ldg(b + 4) + fz * __ldg(b + 7);
    float csz = fx * __ldg(b + 2) + fy * __ldg(b + 5) + fz * __ldg(b + 8);

    const float* pi = pos + 3u * (size_t)i;
    const float* pj = pos + 3u * (size_t)j;
    float drx = __ldg(pj + 0) - __ldg(pi + 0) + csx;
    float dry = __ldg(pj + 1) - __ldg(pi + 1) + csy;
    float drz = __ldg(pj + 2) - __ldg(pi + 2) + csz;

    float w = sqrtf(drx * drx + dry * dry + drz * drz);

    size_t Es = (size_t)E;
    out[e]          = (float)i;
    out[Es + e]     = (float)j;
    out[2 * Es + e] = w;
    float* v = out + 3 * Es + 3u * (size_t)e;
    v[0] = -drx; v[1] = -dry; v[2] = -drz;
    float* sh = out + 6 * Es + 3u * (size_t)e;
    sh[0] = fx; sh[1] = fy; sh[2] = fz;
}

extern "C" void kernel_launch(void* const* d_in, const int* in_sizes, int n_in,
                              void* d_out, int out_size)
{
    const float* pos    = (const float*)d_in[0];
    const float* box    = (const float*)d_in[1];
    const int*   ei     = (const int*)  d_in[2];
    const int*   shifts = (const int*)  d_in[3];
    const int*   batch  = (const int*)  d_in[4];

    int E       = in_sizes[4];
    int n_atoms = in_sizes[0] / 3;
    int n_boxes = in_sizes[1] / 9;
    float* out  = (float*)d_out;

    bool fast = (E % 4 == 0) && (n_atoms <= MAX_ATOMS_PAD) && (n_boxes == 1)
                && ((long long)out_size == 9LL * E);

    if (fast) {
        pd_minmax<<<MM_BLOCKS, 256>>>(pos, 3 * n_atoms);
        pd_quant<<<(n_atoms + 255) / 256, 256>>>(pos, n_atoms);
        int E4 = E / 4;
        pd_kernel_q4<<<(E4 + 255) / 256, 256>>>(box, ei, shifts, out, E4);
    } else {
        pd_kernel_full<<<(E + 255) / 256, 256>>>(pos, box, ei, shifts, batch,
                                                 out, E, n_boxes);
    }
}

// round 5
// speedup vs baseline: 1.0645x; 1.0645x over previous
#include <cuda_runtime.h>
#include <cuda_bf16.h>
#include <stdint.h>

// PeriodicDistance — float4-padded gathers + occupancy-optimized main kernel
// (2 edges/thread, ~36 regs, launch_bounds(256,7) -> ~87% occ).
//
// Output layout (float32, flattened tuple in return order):
//   [0,E) ei0 | [E,2E) ei1 | [2E,3E) weight | [3E,6E) vec[E,3] | [6E,9E) shifts[E,3]

#define MAX_ATOMS_PAD (1 << 19)   // 524288 atoms * 16B = 8 MB static scratch
__device__ float4 g_pos4[MAX_ATOMS_PAD];

// --- prologue: pos[N,3] -> g_pos4[N] (16B rows), 4 atoms/thread vectorized ---
__global__ void __launch_bounds__(256)
pd_pad_pos(const float* __restrict__ pos, int n_atoms)
{
    int t = blockIdx.x * blockDim.x + threadIdx.x;
    int a0 = 4 * t;
    if (a0 >= n_atoms) return;
    if (a0 + 3 < n_atoms) {
        const float4* p4 = (const float4*)(pos) + 3u * (size_t)t;
        float4 v0 = __ldg(p4 + 0);   // x0 y0 z0 x1
        float4 v1 = __ldg(p4 + 1);   // y1 z1 x2 y2
        float4 v2 = __ldg(p4 + 2);   // z2 x3 y3 z3
        g_pos4[a0 + 0] = make_float4(v0.x, v0.y, v0.z, 0.0f);
        g_pos4[a0 + 1] = make_float4(v0.w, v1.x, v1.y, 0.0f);
        g_pos4[a0 + 2] = make_float4(v1.z, v1.w, v2.x, 0.0f);
        g_pos4[a0 + 3] = make_float4(v2.y, v2.z, v2.w, 0.0f);
    } else {
        for (int a = a0; a < n_atoms; a++) {
            const float* p = pos + 3u * (size_t)a;
            g_pos4[a] = make_float4(__ldg(p + 0), __ldg(p + 1), __ldg(p + 2), 0.0f);
        }
    }
}

// --- main: 2 edges per thread ---
__global__ void __launch_bounds__(256, 7)
pd_kernel_v2(const float* __restrict__ box,
             const int*   __restrict__ ei,
             const int*   __restrict__ shifts,
             float*       __restrict__ out,
             int E2)     // E/2
{
    int t = blockIdx.x * blockDim.x + threadIdx.x;
    if (t >= E2) return;

    size_t Es = 2u * (size_t)E2;    // E

    const int2* ei2 = (const int2*)ei;
    int2 ia = __ldg(ei2 + t);             // src of edges 2t, 2t+1
    int2 ib = __ldg(ei2 + E2 + t);        // dst

    // issue all 4 gathers first (max MLP)
    float4 pa0 = g_pos4[ia.x];
    float4 pa1 = g_pos4[ia.y];
    float4 pb0 = g_pos4[ib.x];
    float4 pb1 = g_pos4[ib.y];

    // shifts: 6 ints per thread, 8B-aligned int2 loads
    const int2* sh2 = (const int2*)shifts;
    int2 s01 = __ldg(sh2 + 3u * (size_t)t + 0);   // e0: sx, sy
    int2 s23 = __ldg(sh2 + 3u * (size_t)t + 1);   // e0: sz | e1: sx
    int2 s45 = __ldg(sh2 + 3u * (size_t)t + 2);   // e1: sy, sz
    float fx0 = (float)s01.x, fy0 = (float)s01.y, fz0 = (float)s23.x;
    float fx1 = (float)s23.y, fy1 = (float)s45.x, fz1 = (float)s45.y;

    float b00 = __ldg(box + 0), b01 = __ldg(box + 1), b02 = __ldg(box + 2);
    float b10 = __ldg(box + 3), b11 = __ldg(box + 4), b12 = __ldg(box + 5);
    float b20 = __ldg(box + 6), b21 = __ldg(box + 7), b22 = __ldg(box + 8);

    float drx0 = pb0.x - pa0.x + fx0 * b00 + fy0 * b10 + fz0 * b20;
    float dry0 = pb0.y - pa0.y + fx0 * b01 + fy0 * b11 + fz0 * b21;
    float drz0 = pb0.z - pa0.z + fx0 * b02 + fy0 * b12 + fz0 * b22;
    float drx1 = pb1.x - pa1.x + fx1 * b00 + fy1 * b10 + fz1 * b20;
    float dry1 = pb1.y - pa1.y + fx1 * b01 + fy1 * b11 + fz1 * b21;
    float drz1 = pb1.z - pa1.z + fx1 * b02 + fy1 * b12 + fz1 * b22;

    float w0 = sqrtf(drx0 * drx0 + dry0 * dry0 + drz0 * drz0);
    float w1 = sqrtf(drx1 * drx1 + dry1 * dry1 + drz1 * drz1);

    // stores — all float2, 8B aligned (E even)
    ((float2*)(out))[t]           = make_float2((float)ia.x, (float)ia.y);
    ((float2*)(out + Es))[t]      = make_float2((float)ib.x, (float)ib.y);
    ((float2*)(out + 2 * Es))[t]  = make_float2(w0, w1);

    float2* ov = (float2*)(out + 3 * Es) + 3u * (size_t)t;
    ov[0] = make_float2(-drx0, -dry0);
    ov[1] = make_float2(-drz0, -drx1);
    ov[2] = make_float2(-dry1, -drz1);

    float2* os = (float2*)(out + 6 * Es) + 3u * (size_t)t;
    os[0] = make_float2(fx0, fy0);
    os[1] = make_float2(fz0, fx1);
    os[2] = make_float2(fy1, fz1);
}

// --- exact scalar fallback (general shapes) ---
__global__ void __launch_bounds__(256)
pd_kernel_full(const float* __restrict__ pos,
               const float* __restrict__ box,
               const int*   __restrict__ ei,
               const int*   __restrict__ shifts,
               const int*   __restrict__ batch,
               float*       __restrict__ out,
               int E, int n_boxes)
{
    int e = blockIdx.x * blockDim.x + threadIdx.x;
    if (e >= E) return;

    int i = __ldg(ei + e);
    int j = __ldg(ei + (size_t)E + e);
    const int* sp = shifts + 3u * (size_t)e;
    float fx = (float)__ldg(sp + 0);
    float fy = (float)__ldg(sp + 1);
    float fz = (float)__ldg(sp + 2);

    const float* b = box;
    if (n_boxes > 1) b = box + 9u * (size_t)__ldg(batch + e);
    float csx = fx * __ldg(b + 0) + fy * __ldg(b + 3) + fz * __ldg(b + 6);
    float csy = fx * __ldg(b + 1) + fy * __ldg(b + 4) + fz * __ldg(b + 7);
    float csz = fx * __ldg(b + 2) + fy * __ldg(b + 5) + fz * __ldg(b + 8);

    const float* pi = pos + 3u * (size_t)i;
    const float* pj = pos + 3u * (size_t)j;
    float drx = __ldg(pj + 0) - __ldg(pi + 0) + csx;
    float dry = __ldg(pj + 1) - __ldg(pi + 1) + csy;
    float drz = __ldg(pj + 2) - __ldg(pi + 2) + csz;

    float w = sqrtf(drx * drx + dry * dry + drz * drz);

    size_t Es = (size_t)E;
    out[e]          = (float)i;
    out[Es + e]     = (float)j;
    out[2 * Es + e] = w;
    float* v = out + 3 * Es + 3u * (size_t)e;
    v[0] = -drx; v[1] = -dry; v[2] = -drz;
    float* sh = out + 6 * Es + 3u * (size_t)e;
    sh[0] = fx; sh[1] = fy; sh[2] = fz;
}

extern "C" void kernel_launch(void* const* d_in, const int* in_sizes, int n_in,
                              void* d_out, int out_size)
{
    const float* pos    = (const float*)d_in[0];
    const float* box    = (const float*)d_in[1];
    const int*   ei     = (const int*)  d_in[2];
    const int*   shifts = (const int*)  d_in[3];
    const int*   batch  = (const int*)  d_in[4];

    int E       = in_sizes[4];
    int n_atoms = in_sizes[0] / 3;
    int n_boxes = in_sizes[1] / 9;
    float* out  = (float*)d_out;

    bool fast = (E % 2 == 0) && (n_atoms <= MAX_ATOMS_PAD) && (n_boxes == 1)
                && ((long long)out_size == 9LL * E);

    if (fast) {
        int pt = (n_atoms + 3) / 4;
        pd_pad_pos<<<(pt + 255) / 256, 256>>>(pos, n_atoms);
        int E2 = E / 2;
        pd_kernel_v2<<<(E2 + 255) / 256, 256>>>(box, ei, shifts, out, E2);
    } else {
        pd_kernel_full<<<(E + 255) / 256, 256>>>(pos, box, ei, shifts, batch,
                                                 out, E, n_boxes);
    }
}